// round 10
// baseline (speedup 1.0000x reference)
#include <cuda_runtime.h>
#include <cstddef>
#include <cstdint>

// VarConvND: 4096 independent GEMMs [B=64 x K=288] x [K=288 x C_OUT=16].
// tf32 MMA, warps split batch, K double-buffered (6 chunks x 48 rows).
//   out[b,c,s] = sum_k u[b,k]*w[k,c] + bias[s]*sum_k w[k,c]

#define S_TOT 4096
#define KK    288
#define CO    16
#define CI    32
#define BB    64
#define HH    64
#define WW    64
#define P_TOT (CI*HH*WW)            // 131072

#define AST   72                    // X row stride (words): A-frag reads hit 32 banks
#define WST   24                    // W row stride (words): B-frag reads hit 32 banks
#define CKR   48                    // k-rows per chunk
#define NCH   6                     // chunks (6*48 = 288)

#define W_WORDS   (KK*WST)          // 6912
#define XB_WORDS  (CKR*AST)         // 3456
#define XB0_OFF   W_WORDS
#define XB1_OFF   (W_WORDS + XB_WORDS)
#define CSUM_OFF  (W_WORDS + 2*XB_WORDS)
#define SMEM_WORDS (CSUM_OFF + 16)
#define SMEM_BYTES (SMEM_WORDS * 4)   // 55,360

__device__ float g_Xt[(size_t)P_TOT * BB];        // X^T, tf32-rounded, [p][b]
__device__ float g_Os[(size_t)S_TOT * BB * CO];   // out scratch [s][b*16+c]

__device__ __forceinline__ unsigned f2tf(float f)
{
    unsigned u;
    asm("cvt.rna.tf32.f32 %0, %1;" : "=r"(u) : "f"(f));
    return u;
}

// ---------- transpose + tf32-round: X[b][p] -> Xt[p][b] ----------
// 128 p x 64 b per block; 8 LDG.128 in flight per thread.
__global__ __launch_bounds__(256)
void transpose_in(const float* __restrict__ X, float* __restrict__ Xt)
{
    __shared__ float tt[2][64][65];
    const int tid = threadIdx.x;
    const int p0  = blockIdx.x * 128;

    float4 v[8];
    #pragma unroll
    for (int t = 0; t < 2; t++)
        #pragma unroll
        for (int i = 0; i < 4; i++) {
            const int u = tid + 256 * i;
            const int b = u >> 4;
            const int q = u & 15;
            v[t * 4 + i] = *(const float4*)(X + (size_t)b * P_TOT + p0 + t * 64 + 4 * q);
        }
    #pragma unroll
    for (int t = 0; t < 2; t++)
        #pragma unroll
        for (int i = 0; i < 4; i++) {
            const int u = tid + 256 * i;
            const int b = u >> 4;
            const int q = u & 15;
            tt[t][4 * q + 0][b] = v[t * 4 + i].x;
            tt[t][4 * q + 1][b] = v[t * 4 + i].y;
            tt[t][4 * q + 2][b] = v[t * 4 + i].z;
            tt[t][4 * q + 3][b] = v[t * 4 + i].w;
        }
    __syncthreads();
    #pragma unroll
    for (int t = 0; t < 2; t++)
        #pragma unroll
        for (int i = 0; i < 4; i++) {
            const int u  = tid + 256 * i;
            const int p  = u >> 4;
            const int bq = u & 15;
            float4 o;
            o.x = __uint_as_float(f2tf(tt[t][p][4 * bq + 0]));
            o.y = __uint_as_float(f2tf(tt[t][p][4 * bq + 1]));
            o.z = __uint_as_float(f2tf(tt[t][p][4 * bq + 2]));
            o.w = __uint_as_float(f2tf(tt[t][p][4 * bq + 3]));
            *(float4*)(Xt + (size_t)(p0 + t * 64 + p) * BB + 4 * bq) = o;
        }
}

// ---------- output transpose: Os[s][bc] -> out[bc][s], 64x64 tiles ----------
__global__ __launch_bounds__(256)
void transpose_out(const float* __restrict__ Os, float* __restrict__ out)
{
    __shared__ float tt[64][65];
    const int tid = threadIdx.x;
    const int bc0 = blockIdx.x * 64;
    const int s0  = blockIdx.y * 64;

    #pragma unroll
    for (int i = 0; i < 4; i++) {
        const int u  = tid + 256 * i;
        const int sl = u >> 4;
        const int q  = u & 15;
        float4 v = *(const float4*)(Os + (size_t)(s0 + sl) * (BB * CO) + bc0 + 4 * q);
        tt[4 * q + 0][sl] = v.x;
        tt[4 * q + 1][sl] = v.y;
        tt[4 * q + 2][sl] = v.z;
        tt[4 * q + 3][sl] = v.w;
    }
    __syncthreads();
    #pragma unroll
    for (int i = 0; i < 4; i++) {
        const int u  = tid + 256 * i;
        const int bl = u >> 4;
        const int sq = u & 15;
        float4 o;
        o.x = tt[bl][4 * sq + 0];
        o.y = tt[bl][4 * sq + 1];
        o.z = tt[bl][4 * sq + 2];
        o.w = tt[bl][4 * sq + 3];
        *(float4*)(out + (size_t)(bc0 + bl) * S_TOT + s0 + 4 * sq) = o;
    }
}

// ---------- main kernel ----------
__device__ __forceinline__ void cp16(unsigned dst, const void* src, bool ok)
{
    int sz = ok ? 16 : 0;
    asm volatile("cp.async.cg.shared.global [%0], [%1], 16, %2;\n"
                 :: "r"(dst), "l"(src), "r"(sz) : "memory");
}
#define CP_COMMIT() asm volatile("cp.async.commit_group;\n" ::: "memory")
#define CP_WAIT(N)  asm volatile("cp.async.wait_group %0;\n" :: "n"(N) : "memory")

__global__ __launch_bounds__(128)
void varconv_mma(const float* __restrict__ Wg,
                 const float* __restrict__ bias,
                 float* __restrict__ Os)
{
    extern __shared__ float smf[];
    const unsigned smb = (unsigned)__cvta_generic_to_shared(smf);

    const int s    = blockIdx.x;
    const int y    = s >> 6;
    const int x    = s & 63;
    const int tid  = threadIdx.x;
    const int lane = tid & 31;
    const int wid  = tid >> 5;

    const float* wp = Wg + (size_t)s * (KK * CO);

    // ---- stage W (288x16 fp32, row stride 24) via cp.async ----
    {
        const int k0 = tid >> 2;
        const int q  = tid & 3;
        #pragma unroll
        for (int i = 0; i < 9; i++) {
            const int k = k0 + 32 * i;
            cp16(smb + (unsigned)(k * WST + q * 4) * 4u, wp + k * CO + q * 4, true);
        }
    }

    // ---- stage one X chunk (48 k-rows x 64 batches) ----
    auto stage_x = [&](int chunk, int bufoff) {
        const int r0 = tid >> 4;          // 0..7
        const int q  = tid & 15;          // 16B unit in row
        #pragma unroll
        for (int i = 0; i < 6; i++) {
            const int r   = r0 + 8 * i;   // 0..47
            const int k   = chunk * CKR + r;
            const int cl  = k / 9;
            const int tap = k - cl * 9;
            const int t3  = tap / 3;
            const int yy  = y + t3 - 1;
            const int xx  = x + (tap - 3 * t3) - 1;
            const bool ok = ((unsigned)yy < (unsigned)HH) & ((unsigned)xx < (unsigned)WW);
            const float* src = ok
                ? g_Xt + ((size_t)((cl << 12) + (yy << 6) + xx) << 6) + q * 4
                : g_Xt;
            cp16(smb + (unsigned)(bufoff + r * AST + q * 4) * 4u, src, ok);
        }
    };

    stage_x(0, XB0_OFF);
    CP_COMMIT();                          // G0 = W + X0
    stage_x(1, XB1_OFF);
    CP_COMMIT();                          // G1 = X1

    // fragment roles
    const int cc = lane & 3;
    const int r4 = lane >> 2;
    // batch(row) = wid*16 + 2*(row&7) + (row>>3): rows (r4, r4+8) adjacent words
    const int aoff = cc * AST + wid * 16 + 2 * r4;        // + i*576; a2/a3 at +4*AST
    const int woff = cc * WST + r4;                       // + k8*8*WST; +8 for c+8

    float acc[2][4] = {};
    float cs0 = 0.f, cs1 = 0.f;

    auto compute = [&](int bufoff, int chunk) {
        #pragma unroll
        for (int i = 0; i < 6; i++) {
            const int ab = bufoff + i * (8 * AST) + aoff;
            const uint2 a01 = *(const uint2*)&smf[ab];
            const uint2 a23 = *(const uint2*)&smf[ab + 4 * AST];
            const int wb = (chunk * CKR + i * 8) * WST + woff;
            const float w0 = smf[wb];
            const float w1 = smf[wb + 4 * WST];
            const float w2 = smf[wb + 8];
            const float w3 = smf[wb + 4 * WST + 8];
            cs0 += w0 + w1;
            cs1 += w2 + w3;
            const unsigned b00 = f2tf(w0), b01 = f2tf(w1);
            const unsigned b10 = f2tf(w2), b11 = f2tf(w3);
            asm volatile(
                "mma.sync.aligned.m16n8k8.row.col.f32.tf32.tf32.f32 "
                "{%0,%1,%2,%3}, {%4,%5,%6,%7}, {%8,%9}, {%0,%1,%2,%3};"
                : "+f"(acc[0][0]), "+f"(acc[0][1]), "+f"(acc[0][2]), "+f"(acc[0][3])
                : "r"(a01.x), "r"(a01.y), "r"(a23.x), "r"(a23.y),
                  "r"(b00), "r"(b01));
            asm volatile(
                "mma.sync.aligned.m16n8k8.row.col.f32.tf32.tf32.f32 "
                "{%0,%1,%2,%3}, {%4,%5,%6,%7}, {%8,%9}, {%0,%1,%2,%3};"
                : "+f"(acc[1][0]), "+f"(acc[1][1]), "+f"(acc[1][2]), "+f"(acc[1][3])
                : "r"(a01.x), "r"(a01.y), "r"(a23.x), "r"(a23.y),
                  "r"(b10), "r"(b11));
        }
    };

    #pragma unroll
    for (int ch = 0; ch < NCH; ch++) {
        if (ch < NCH - 1) { CP_WAIT(1); } else { CP_WAIT(0); }
        __syncthreads();                          // X(ch) (+W on ch0) visible
        compute((ch & 1) ? XB1_OFF : XB0_OFF, ch);
        if (ch < NCH - 2) {
            __syncthreads();                      // buffer readers done
            stage_x(ch + 2, (ch & 1) ? XB1_OFF : XB0_OFF);
            CP_COMMIT();
        }
    }

    // ---- colsum: reduce over cc lanes; warp 0 publishes ----
    cs0 += __shfl_xor_sync(0xffffffffu, cs0, 1);
    cs0 += __shfl_xor_sync(0xffffffffu, cs0, 2);
    cs1 += __shfl_xor_sync(0xffffffffu, cs1, 1);
    cs1 += __shfl_xor_sync(0xffffffffu, cs1, 2);
    if (wid == 0 && cc == 0) {
        smf[CSUM_OFF + r4]     = cs0;   // c = r4
        smf[CSUM_OFF + 8 + r4] = cs1;   // c = r4 + 8
    }
    __syncthreads();

    // ---- epilogue: STG.64 pairs into Os[s][b*16+c] ----
    {
        const float bval = bias[s];
        float* os = Os + (size_t)s * (BB * CO);
        const int blo = wid * 16 + 2 * r4;        // rows r4 / r4+8 -> b, b+1
        #pragma unroll
        for (int nt = 0; nt < 2; nt++) {
            const int c = nt * 8 + 2 * cc;
            const float t0 = bval * smf[CSUM_OFF + c];
            const float t1 = bval * smf[CSUM_OFF + c + 1];
            float2 v0 = make_float2(acc[nt][0] + t0, acc[nt][1] + t1);
            float2 v1 = make_float2(acc[nt][2] + t0, acc[nt][3] + t1);
            *(float2*)&os[blo * CO + c]       = v0;
            *(float2*)&os[(blo + 1) * CO + c] = v1;
        }
    }
}

extern "C" void kernel_launch(void* const* d_in, const int* in_sizes, int n_in,
                              void* d_out, int out_size)
{
    const float* X    = (const float*)d_in[0];
    const float* Wg   = (const float*)d_in[1];
    const float* bias = (const float*)d_in[2];
    float* out        = (float*)d_out;
    (void)in_sizes; (void)n_in; (void)out_size;

    float *Xt = nullptr, *Os = nullptr;
    cudaGetSymbolAddress((void**)&Xt, g_Xt);
    cudaGetSymbolAddress((void**)&Os, g_Os);

    cudaFuncSetAttribute(varconv_mma,
                         cudaFuncAttributeMaxDynamicSharedMemorySize, SMEM_BYTES);

    transpose_in<<<P_TOT / 128, 256>>>(X, Xt);

    varconv_mma<<<S_TOT, 128, SMEM_BYTES>>>(Wg, bias, Os);

    transpose_out<<<dim3((BB * CO) / 64, S_TOT / 64), 256>>>(Os, out);
}

// round 11
// speedup vs baseline: 1.4077x; 1.4077x over previous
#include <cuda_runtime.h>
#include <cstddef>
#include <cstdint>

// VarConvND: 4096 independent GEMMs [B=64 x K=288] x [K=288 x C_OUT=16].
// tf32 MMA, warps split batch, K double-buffered (4 chunks x 72 rows).
//   out[b,c,s] = sum_k u[b,k]*w[k,c] + bias[s]*sum_k w[k,c]

#define S_TOT 4096
#define KK    288
#define CO    16
#define CI    32
#define BB    64
#define HH    64
#define WW    64
#define P_TOT (CI*HH*WW)            // 131072

#define AST   72                    // X row stride (words): A-frag reads hit 32 banks
#define WST   24                    // W row stride (words): B-frag reads hit 32 banks
#define CKR   72                    // k-rows per chunk
#define NCH   4                     // chunks

#define W_WORDS   (KK*WST)          // 6912
#define XB_WORDS  (CKR*AST)         // 5184
#define XB0_OFF   W_WORDS
#define XB1_OFF   (W_WORDS + XB_WORDS)
#define CSUM_OFF  (W_WORDS + 2*XB_WORDS)
#define SMEM_WORDS (CSUM_OFF + 16)
#define SMEM_BYTES (SMEM_WORDS * 4)   // 69,248

__device__ float g_Xt[(size_t)P_TOT * BB];        // X^T, tf32-rounded, [p][b]
__device__ float g_Os[(size_t)S_TOT * BB * CO];   // out scratch [s][b*16+c]

__device__ __forceinline__ unsigned f2tf(float f)
{
    unsigned u;
    asm("cvt.rna.tf32.f32 %0, %1;" : "=r"(u) : "f"(f));
    return u;
}

// ---------- transpose + tf32-round: X[b][p] -> Xt[p][b] (R9 verbatim) ----------
__global__ __launch_bounds__(256)
void transpose_in(const float* __restrict__ X, float* __restrict__ Xt)
{
    __shared__ float tt[64][65];
    const int tid = threadIdx.x;
    const int p0  = blockIdx.x * 64;

    #pragma unroll
    for (int i = 0; i < 4; i++) {
        const int u = tid + 256 * i;
        const int b = u >> 4;
        const int q = u & 15;
        float4 v = *(const float4*)(X + (size_t)b * P_TOT + p0 + 4 * q);
        tt[4 * q + 0][b] = v.x;
        tt[4 * q + 1][b] = v.y;
        tt[4 * q + 2][b] = v.z;
        tt[4 * q + 3][b] = v.w;
    }
    __syncthreads();
    #pragma unroll
    for (int i = 0; i < 4; i++) {
        const int u  = tid + 256 * i;
        const int p  = u >> 4;
        const int bq = u & 15;
        float4 o;
        o.x = __uint_as_float(f2tf(tt[p][4 * bq + 0]));
        o.y = __uint_as_float(f2tf(tt[p][4 * bq + 1]));
        o.z = __uint_as_float(f2tf(tt[p][4 * bq + 2]));
        o.w = __uint_as_float(f2tf(tt[p][4 * bq + 3]));
        *(float4*)(Xt + (size_t)(p0 + p) * BB + 4 * bq) = o;
    }
}

// ---------- output transpose: Os[s][bc] -> out[bc][s], 64x64 float4 tiles ----------
__global__ __launch_bounds__(256)
void transpose_out(const float* __restrict__ Os, float* __restrict__ out)
{
    __shared__ float tt[64][65];
    const int tid = threadIdx.x;
    const int bc0 = blockIdx.x * 64;
    const int s0  = blockIdx.y * 64;

    #pragma unroll
    for (int i = 0; i < 4; i++) {
        const int u  = tid + 256 * i;
        const int sl = u >> 4;
        const int q  = u & 15;
        float4 v = *(const float4*)(Os + (size_t)(s0 + sl) * (BB * CO) + bc0 + 4 * q);
        tt[4 * q + 0][sl] = v.x;
        tt[4 * q + 1][sl] = v.y;
        tt[4 * q + 2][sl] = v.z;
        tt[4 * q + 3][sl] = v.w;
    }
    __syncthreads();
    #pragma unroll
    for (int i = 0; i < 4; i++) {
        const int u  = tid + 256 * i;
        const int bl = u >> 4;
        const int sq = u & 15;
        float4 o;
        o.x = tt[bl][4 * sq + 0];
        o.y = tt[bl][4 * sq + 1];
        o.z = tt[bl][4 * sq + 2];
        o.w = tt[bl][4 * sq + 3];
        *(float4*)(out + (size_t)(bc0 + bl) * S_TOT + s0 + 4 * sq) = o;
    }
}

// ---------- main kernel ----------
__device__ __forceinline__ void cp16(unsigned dst, const void* src, bool ok)
{
    int sz = ok ? 16 : 0;
    asm volatile("cp.async.cg.shared.global [%0], [%1], 16, %2;\n"
                 :: "r"(dst), "l"(src), "r"(sz) : "memory");
}
#define CP_COMMIT() asm volatile("cp.async.commit_group;\n" ::: "memory")
#define CP_WAIT(N)  asm volatile("cp.async.wait_group %0;\n" :: "n"(N) : "memory")

__global__ __launch_bounds__(128)
void varconv_mma(const float* __restrict__ Wg,
                 const float* __restrict__ bias,
                 float* __restrict__ Os)
{
    extern __shared__ float smf[];
    const unsigned smb = (unsigned)__cvta_generic_to_shared(smf);

    const int s    = blockIdx.x;
    const int y    = s >> 6;
    const int x    = s & 63;
    const int tid  = threadIdx.x;
    const int lane = tid & 31;
    const int wid  = tid >> 5;

    const float* wp = Wg + (size_t)s * (KK * CO);

    // ---- stage W (288x16 fp32, row stride 24) via cp.async ----
    {
        const int k0 = tid >> 2;
        const int q  = tid & 3;
        #pragma unroll
        for (int i = 0; i < 9; i++) {
            const int k = k0 + 32 * i;
            cp16(smb + (unsigned)(k * WST + q * 4) * 4u, wp + k * CO + q * 4, true);
        }
    }

    // ---- stage one X chunk (72 k-rows x 64 batches, tf32 bits) ----
    auto stage_x = [&](int chunk, int bufoff) {
        const int r0 = tid >> 4;          // 0..7
        const int q  = tid & 15;          // 16B unit in row
        #pragma unroll
        for (int i = 0; i < 9; i++) {
            const int r   = r0 + 8 * i;   // 0..71
            const int k   = chunk * CKR + r;
            const int cl  = k / 9;
            const int tap = k - cl * 9;
            const int t3  = tap / 3;
            const int yy  = y + t3 - 1;
            const int xx  = x + (tap - 3 * t3) - 1;
            const bool ok = ((unsigned)yy < (unsigned)HH) & ((unsigned)xx < (unsigned)WW);
            const float* src = ok
                ? g_Xt + ((size_t)((cl << 12) + (yy << 6) + xx) << 6) + q * 4
                : g_Xt;
            cp16(smb + (unsigned)(bufoff + r * AST + q * 4) * 4u, src, ok);
        }
    };

    stage_x(0, XB0_OFF);
    CP_COMMIT();                          // G0 = W + X0
    stage_x(1, XB1_OFF);
    CP_COMMIT();                          // G1 = X1

    // fragment roles (batch permuted: m-row r -> batch wid*16 + 2*(r&7) + (r>>3))
    const int cc = lane & 3;
    const int r4 = lane >> 2;
    const int aoff = cc * AST + wid * 16 + 2 * r4;   // rows (r4, r4+8) adjacent words
    const int woff = cc * WST + r4;

    float acc[2][4] = {};
    float cs0 = 0.f, cs1 = 0.f;

    auto compute = [&](int bufoff, int chunk) {
        #pragma unroll
        for (int i = 0; i < 9; i++) {
            const int ab = bufoff + i * (8 * AST) + aoff;
            const uint2 a01 = *(const uint2*)&smf[ab];
            const uint2 a23 = *(const uint2*)&smf[ab + 4 * AST];
            const int wb = (chunk * CKR + i * 8) * WST + woff;
            const float w0 = smf[wb];
            const float w1 = smf[wb + 4 * WST];
            const float w2 = smf[wb + 8];
            const float w3 = smf[wb + 4 * WST + 8];
            cs0 += w0 + w1;
            cs1 += w2 + w3;
            const unsigned b00 = f2tf(w0), b01 = f2tf(w1);
            const unsigned b10 = f2tf(w2), b11 = f2tf(w3);
            asm volatile(
                "mma.sync.aligned.m16n8k8.row.col.f32.tf32.tf32.f32 "
                "{%0,%1,%2,%3}, {%4,%5,%6,%7}, {%8,%9}, {%0,%1,%2,%3};"
                : "+f"(acc[0][0]), "+f"(acc[0][1]), "+f"(acc[0][2]), "+f"(acc[0][3])
                : "r"(a01.x), "r"(a01.y), "r"(a23.x), "r"(a23.y),
                  "r"(b00), "r"(b01));
            asm volatile(
                "mma.sync.aligned.m16n8k8.row.col.f32.tf32.tf32.f32 "
                "{%0,%1,%2,%3}, {%4,%5,%6,%7}, {%8,%9}, {%0,%1,%2,%3};"
                : "+f"(acc[1][0]), "+f"(acc[1][1]), "+f"(acc[1][2]), "+f"(acc[1][3])
                : "r"(a01.x), "r"(a01.y), "r"(a23.x), "r"(a23.y),
                  "r"(b10), "r"(b11));
        }
    };

    CP_WAIT(1); __syncthreads();          // W + chunk0 visible
    compute(XB0_OFF, 0);
    __syncthreads();
    stage_x(2, XB0_OFF); CP_COMMIT();

    CP_WAIT(1); __syncthreads();          // chunk1 visible
    compute(XB1_OFF, 1);
    __syncthreads();
    stage_x(3, XB1_OFF); CP_COMMIT();

    CP_WAIT(1); __syncthreads();          // chunk2 visible
    compute(XB0_OFF, 2);

    CP_WAIT(0); __syncthreads();          // chunk3 visible
    compute(XB1_OFF, 3);

    // ---- colsum: reduce over cc lanes within quads; warp 0 publishes ----
    cs0 += __shfl_xor_sync(0xffffffffu, cs0, 1);
    cs0 += __shfl_xor_sync(0xffffffffu, cs0, 2);
    cs1 += __shfl_xor_sync(0xffffffffu, cs1, 1);
    cs1 += __shfl_xor_sync(0xffffffffu, cs1, 2);
    if (wid == 0 && cc == 0) {
        smf[CSUM_OFF + r4]     = cs0;   // c = r4
        smf[CSUM_OFF + 8 + r4] = cs1;   // c = r4 + 8
    }
    __syncthreads();

    // ---- epilogue: STG.64 pairs into Os[s][b*16+c] ----
    {
        const float bval = bias[s];
        float* os = Os + (size_t)s * (BB * CO);
        const int blo = wid * 16 + 2 * r4;        // rows r4 / r4+8 -> b, b+1
        #pragma unroll
        for (int nt = 0; nt < 2; nt++) {
            const int c = nt * 8 + 2 * cc;
            const float t0 = bval * smf[CSUM_OFF + c];
            const float t1 = bval * smf[CSUM_OFF + c + 1];
            float2 v0 = make_float2(acc[nt][0] + t0, acc[nt][1] + t1);
            float2 v1 = make_float2(acc[nt][2] + t0, acc[nt][3] + t1);
            *(float2*)&os[blo * CO + c]       = v0;
            *(float2*)&os[(blo + 1) * CO + c] = v1;
        }
    }
}

extern "C" void kernel_launch(void* const* d_in, const int* in_sizes, int n_in,
                              void* d_out, int out_size)
{
    const float* X    = (const float*)d_in[0];
    const float* Wg   = (const float*)d_in[1];
    const float* bias = (const float*)d_in[2];
    float* out        = (float*)d_out;
    (void)in_sizes; (void)n_in; (void)out_size;

    float *Xt = nullptr, *Os = nullptr;
    cudaGetSymbolAddress((void**)&Xt, g_Xt);
    cudaGetSymbolAddress((void**)&Os, g_Os);

    cudaFuncSetAttribute(varconv_mma,
                         cudaFuncAttributeMaxDynamicSharedMemorySize, SMEM_BYTES);

    transpose_in<<<P_TOT / 64, 256>>>(X, Xt);

    varconv_mma<<<S_TOT, 128, SMEM_BYTES>>>(Wg, bias, Os);

    transpose_out<<<dim3((BB * CO) / 64, S_TOT / 64), 256>>>(Os, out);
}